// round 1
// baseline (speedup 1.0000x reference)
#include <cuda_runtime.h>
#include <math.h>

#define N_NODES 100000
#define D 128
#define D_LAT 64
#define N_EDGES 1600000

// Scratch (device globals: allocation-free, graph-capture safe)
__device__ float g_aggr[(size_t)N_NODES * D];
__device__ float g_hA[(size_t)N_NODES * D];
__device__ float g_hB[(size_t)N_NODES * D];
__device__ float g_inv[N_NODES];
__device__ float g_pool[D];

// ---------------------------------------------------------------------------
__global__ void zero_kernel(float4* __restrict__ p, int n4) {
    int i = blockIdx.x * blockDim.x + threadIdx.x;
    float4 z = make_float4(0.f, 0.f, 0.f, 0.f);
    for (; i < n4; i += gridDim.x * blockDim.x) p[i] = z;
}

// in-degree counts (as float, later inverted)
__global__ void count_kernel(const int* __restrict__ dst, float* __restrict__ cnt) {
    int e = blockIdx.x * blockDim.x + threadIdx.x;
    if (e < N_EDGES) atomicAdd(&cnt[dst[e]], 1.0f);
}

__global__ void inv_kernel(float* __restrict__ c) {
    int i = blockIdx.x * blockDim.x + threadIdx.x;
    if (i < N_NODES) {
        float v = c[i];
        c[i] = (v > 0.f) ? (1.0f / v) : 0.0f;
    }
}

// one warp per edge: lane l moves floats [4l, 4l+4) of the 128-dim feature
__global__ void scatter_kernel(const float* __restrict__ x,
                               const int* __restrict__ src,
                               const int* __restrict__ dst,
                               float* __restrict__ aggr) {
    long long t = (long long)blockIdx.x * blockDim.x + threadIdx.x;
    int e    = (int)(t >> 5);
    int lane = (int)(t & 31);
    if (e >= N_EDGES) return;
    int s = __ldg(&src[e]);
    int d = __ldg(&dst[e]);
    float4 v = __ldg(((const float4*)(x + (size_t)s * D)) + lane);
    float* a = aggr + (size_t)d * D + lane * 4;
    atomicAdd(a + 0, v.x);
    atomicAdd(a + 1, v.y);
    atomicAdd(a + 2, v.z);
    atomicAdd(a + 3, v.w);
}

// ---------------------------------------------------------------------------
// Fused SAGE layer: out = relu( (aggr * inv_deg) @ Wl + xin @ Wr + b )
// Implemented as a [M,256] x [256,128] SGEMM: K<128 -> (aggr,Wl), K>=128 -> (xin,Wr).
// BM=128, BN=128, BK=16, 256 threads, 8x8 microtile.
__global__ __launch_bounds__(256) void sage_gemm(
    const float* __restrict__ aggr, const float* __restrict__ xin,
    const float* __restrict__ inv,
    const float* __restrict__ Wl, const float* __restrict__ Wr,
    const float* __restrict__ bias, float* __restrict__ out)
{
    __shared__ float As[16][128];   // [k][m]
    __shared__ float Bs[16][128];   // [k][n]

    const int t  = threadIdx.x;
    const int m0 = blockIdx.x * 128;
    const int ty = t >> 4;          // 0..15 -> row group
    const int tx = t & 15;          // 0..15 -> col group

    float acc[8][8];
#pragma unroll
    for (int i = 0; i < 8; i++)
#pragma unroll
        for (int j = 0; j < 8; j++) acc[i][j] = 0.f;

    for (int kb = 0; kb < 16; kb++) {
        const bool aph = (kb < 8);                  // aggregation-half of K
        const float* Asrc = aph ? aggr : xin;
        const float* Bsrc = aph ? Wl : Wr;
        const int klocal = (kb & 7) * 16;           // k offset inside source (0..112)

        // --- load A tile (128 rows x 16 k), transposed into As, with deg scaling
#pragma unroll
        for (int i = 0; i < 2; i++) {
            int idx = t + i * 256;
            int row = idx >> 2;                     // 0..127
            int kc  = idx & 3;                      // which float4 of the 16 k's
            int gr  = m0 + row;
            float4 v = make_float4(0.f, 0.f, 0.f, 0.f);
            float  s = 1.f;
            if (gr < N_NODES) {
                v = *((const float4*)(Asrc + (size_t)gr * 128 + klocal + kc * 4));
                if (aph) s = inv[gr];
            }
            As[kc * 4 + 0][row] = v.x * s;
            As[kc * 4 + 1][row] = v.y * s;
            As[kc * 4 + 2][row] = v.z * s;
            As[kc * 4 + 3][row] = v.w * s;
        }
        // --- load B tile (16 k x 128 n)
#pragma unroll
        for (int i = 0; i < 2; i++) {
            int idx = t + i * 256;
            int br  = idx >> 5;                     // 0..15
            int bc  = idx & 31;                     // float4 index within row
            float4 v = *((const float4*)(Bsrc + (size_t)(klocal + br) * 128 + bc * 4));
            *((float4*)&Bs[br][bc * 4]) = v;
        }
        __syncthreads();

#pragma unroll
        for (int k = 0; k < 16; k++) {
            float ra[8], rb[8];
#pragma unroll
            for (int i = 0; i < 8; i++) ra[i] = As[k][ty * 8 + i];
#pragma unroll
            for (int j = 0; j < 8; j++) rb[j] = Bs[k][tx * 8 + j];
#pragma unroll
            for (int i = 0; i < 8; i++)
#pragma unroll
                for (int j = 0; j < 8; j++) acc[i][j] += ra[i] * rb[j];
        }
        __syncthreads();
    }

    // epilogue: bias + relu
#pragma unroll
    for (int i = 0; i < 8; i++) {
        int gr = m0 + ty * 8 + i;
        if (gr >= N_NODES) continue;
        float* orow = out + (size_t)gr * 128;
#pragma unroll
        for (int j = 0; j < 8; j += 4) {
            int col = tx * 8 + j;
            float4 v;
            v.x = fmaxf(acc[i][j + 0] + bias[col + 0], 0.f);
            v.y = fmaxf(acc[i][j + 1] + bias[col + 1], 0.f);
            v.z = fmaxf(acc[i][j + 2] + bias[col + 2], 0.f);
            v.w = fmaxf(acc[i][j + 3] + bias[col + 3], 0.f);
            *((float4*)(orow + col)) = v;
        }
    }
}

// ---------------------------------------------------------------------------
// column-wise sum over all nodes -> pool[128] (then head divides by N)
__global__ void pool_kernel(const float* __restrict__ h, float* __restrict__ pool) {
    __shared__ float4 s[256];
    int t = threadIdx.x;
    int c = t & 31;        // float4 column index (0..31 covers 128 cols)
    int rlane = t >> 5;    // 0..7
    float4 acc = make_float4(0.f, 0.f, 0.f, 0.f);
    const float4* h4 = (const float4*)h;
    for (int r = blockIdx.x * 8 + rlane; r < N_NODES; r += gridDim.x * 8) {
        float4 v = h4[(size_t)r * 32 + c];
        acc.x += v.x; acc.y += v.y; acc.z += v.z; acc.w += v.w;
    }
    s[t] = acc;
    __syncthreads();
    if (rlane == 0) {
#pragma unroll
        for (int i = 1; i < 8; i++) {
            float4 v = s[i * 32 + c];
            acc.x += v.x; acc.y += v.y; acc.z += v.z; acc.w += v.w;
        }
        atomicAdd(&pool[c * 4 + 0], acc.x);
        atomicAdd(&pool[c * 4 + 1], acc.y);
        atomicAdd(&pool[c * 4 + 2], acc.z);
        atomicAdd(&pool[c * 4 + 3], acc.w);
    }
}

__global__ void head_kernel(const float* __restrict__ pool,
                            const float* __restrict__ Wg,
                            const float* __restrict__ bg,
                            float* __restrict__ out) {
    int j = threadIdx.x;
    if (j >= D_LAT) return;
    float acc = bg[j];
    const float invn = 1.0f / (float)N_NODES;
#pragma unroll 8
    for (int k = 0; k < D; k++)
        acc += (pool[k] * invn) * Wg[k * D_LAT + j];
    out[j] = 1.0f / (1.0f + expf(-acc));
}

// ---------------------------------------------------------------------------
extern "C" void kernel_launch(void* const* d_in, const int* in_sizes, int n_in,
                              void* d_out, int out_size) {
    const float* x   = (const float*)d_in[0];
    const int*   ei  = (const int*)d_in[1];
    const float* Wl1 = (const float*)d_in[2];
    const float* Wr1 = (const float*)d_in[3];
    const float* b1  = (const float*)d_in[4];
    const float* Wl2 = (const float*)d_in[5];
    const float* Wr2 = (const float*)d_in[6];
    const float* b2  = (const float*)d_in[7];
    const float* Wl3 = (const float*)d_in[8];
    const float* Wr3 = (const float*)d_in[9];
    const float* b3  = (const float*)d_in[10];
    const float* Wg  = (const float*)d_in[11];
    const float* bg  = (const float*)d_in[12];
    float* out = (float*)d_out;

    const int* src = ei;
    const int* dst = ei + N_EDGES;

    float *aggr, *hA, *hB, *inv, *pool;
    cudaGetSymbolAddress((void**)&aggr, g_aggr);
    cudaGetSymbolAddress((void**)&hA,   g_hA);
    cudaGetSymbolAddress((void**)&hB,   g_hB);
    cudaGetSymbolAddress((void**)&inv,  g_inv);
    cudaGetSymbolAddress((void**)&pool, g_pool);

    const int feat4 = N_NODES * D / 4;   // 3,200,000 float4
    const int scatter_blocks = (N_EDGES * 32) / 256;  // 200,000
    const int gemm_blocks = (N_NODES + 127) / 128;    // 782

    // degree counts -> inverse
    zero_kernel<<<(N_NODES / 4 + 255) / 256, 256>>>((float4*)inv, N_NODES / 4);
    count_kernel<<<(N_EDGES + 255) / 256, 256>>>(dst, inv);
    inv_kernel<<<(N_NODES + 255) / 256, 256>>>(inv);

    // layer 1: x -> hA
    zero_kernel<<<12500, 256>>>((float4*)aggr, feat4);
    scatter_kernel<<<scatter_blocks, 256>>>(x, src, dst, aggr);
    sage_gemm<<<gemm_blocks, 256>>>(aggr, x, inv, Wl1, Wr1, b1, hA);

    // layer 2: hA -> hB
    zero_kernel<<<12500, 256>>>((float4*)aggr, feat4);
    scatter_kernel<<<scatter_blocks, 256>>>(hA, src, dst, aggr);
    sage_gemm<<<gemm_blocks, 256>>>(aggr, hA, inv, Wl2, Wr2, b2, hB);

    // layer 3: hB -> hA
    zero_kernel<<<12500, 256>>>((float4*)aggr, feat4);
    scatter_kernel<<<scatter_blocks, 256>>>(hB, src, dst, aggr);
    sage_gemm<<<gemm_blocks, 256>>>(aggr, hB, inv, Wl3, Wr3, b3, hA);

    // pool + head
    zero_kernel<<<1, 32>>>((float4*)pool, D / 4);
    pool_kernel<<<256, 256>>>(hA, pool);
    head_kernel<<<1, 64>>>(pool, Wg, bg, out);
}

// round 2
// speedup vs baseline: 2.5195x; 2.5195x over previous
#include <cuda_runtime.h>
#include <math.h>

#define N_NODES 100000
#define D 128
#define D_LAT 64
#define N_EDGES 1600000
#define SCAN_BLOCKS ((N_NODES + 255) / 256)   // 391

// Scratch (device globals: allocation-free, graph-capture safe)
__device__ float g_aggr[(size_t)N_NODES * D];
__device__ float g_hA[(size_t)N_NODES * D];
__device__ float g_hB[(size_t)N_NODES * D];
__device__ float g_pool[D];
__device__ int   g_deg[N_NODES];
__device__ int   g_offs[N_NODES];
__device__ int   g_cursor[N_NODES];
__device__ int   g_part[SCAN_BLOCKS];
__device__ int   g_perm[N_EDGES];

// ---------------------------------------------------------------------------
__global__ void zero_i_kernel(int* __restrict__ p, int n) {
    int i = blockIdx.x * blockDim.x + threadIdx.x;
    if (i < n) p[i] = 0;
}
__global__ void zero_f_kernel(float* __restrict__ p, int n) {
    int i = blockIdx.x * blockDim.x + threadIdx.x;
    if (i < n) p[i] = 0.f;
}

// in-degree counts
__global__ void count_kernel(const int* __restrict__ dst, int* __restrict__ deg) {
    int e = blockIdx.x * blockDim.x + threadIdx.x;
    if (e < N_EDGES) atomicAdd(&deg[dst[e]], 1);
}

// block-wise exclusive scan of deg -> offs, block totals -> part
__global__ void scan1_kernel(const int* __restrict__ deg,
                             int* __restrict__ offs, int* __restrict__ part) {
    __shared__ int s[256];
    int t = threadIdx.x;
    int i = blockIdx.x * 256 + t;
    int v = (i < N_NODES) ? deg[i] : 0;
    s[t] = v;
    __syncthreads();
#pragma unroll
    for (int d = 1; d < 256; d <<= 1) {
        int u = (t >= d) ? s[t - d] : 0;
        __syncthreads();
        s[t] += u;
        __syncthreads();
    }
    if (i < N_NODES) offs[i] = s[t] - v;   // exclusive
    if (t == 255) part[blockIdx.x] = s[255];
}

// exclusive scan of part[SCAN_BLOCKS] in one block
__global__ void scan2_kernel(int* __restrict__ part) {
    __shared__ int s[512];
    int t = threadIdx.x;
    int v = (t < SCAN_BLOCKS) ? part[t] : 0;
    s[t] = v;
    __syncthreads();
#pragma unroll
    for (int d = 1; d < 512; d <<= 1) {
        int u = (t >= d) ? s[t - d] : 0;
        __syncthreads();
        s[t] += u;
        __syncthreads();
    }
    if (t < SCAN_BLOCKS) part[t] = s[t] - v;
}

// add block bases; init cursor
__global__ void scan3_kernel(int* __restrict__ offs, const int* __restrict__ part,
                             int* __restrict__ cursor) {
    int i = blockIdx.x * blockDim.x + threadIdx.x;
    if (i < N_NODES) {
        int o = offs[i] + part[i >> 8];
        offs[i] = o;
        cursor[i] = o;
    }
}

// bucket src ids by dst
__global__ void permute_kernel(const int* __restrict__ src, const int* __restrict__ dst,
                               int* __restrict__ cursor, int* __restrict__ perm) {
    int e = blockIdx.x * blockDim.x + threadIdx.x;
    if (e < N_EDGES) {
        int pos = atomicAdd(&cursor[dst[e]], 1);
        perm[pos] = src[e];
    }
}

// ---------------------------------------------------------------------------
// gather-based mean aggregation: one warp per node, lane l owns float4 #l.
// writes aggr = mean of neighbor rows (already scaled by 1/deg).
__global__ __launch_bounds__(256) void gather_aggr(
    const float* __restrict__ x, const int* __restrict__ perm,
    const int* __restrict__ offs, const int* __restrict__ deg,
    float* __restrict__ aggr)
{
    int warp = (blockIdx.x * blockDim.x + threadIdx.x) >> 5;
    int lane = threadIdx.x & 31;
    if (warp >= N_NODES) return;
    int beg = __ldg(&offs[warp]);
    int cnt = __ldg(&deg[warp]);
    int end = beg + cnt;
    const float4* x4 = (const float4*)x;

    float4 acc = make_float4(0.f, 0.f, 0.f, 0.f);
    int e = beg;
    for (; e + 4 <= end; e += 4) {
        int s0 = __ldg(&perm[e + 0]);
        int s1 = __ldg(&perm[e + 1]);
        int s2 = __ldg(&perm[e + 2]);
        int s3 = __ldg(&perm[e + 3]);
        float4 v0 = __ldg(x4 + (size_t)s0 * 32 + lane);
        float4 v1 = __ldg(x4 + (size_t)s1 * 32 + lane);
        float4 v2 = __ldg(x4 + (size_t)s2 * 32 + lane);
        float4 v3 = __ldg(x4 + (size_t)s3 * 32 + lane);
        acc.x += v0.x + v1.x + v2.x + v3.x;
        acc.y += v0.y + v1.y + v2.y + v3.y;
        acc.z += v0.z + v1.z + v2.z + v3.z;
        acc.w += v0.w + v1.w + v2.w + v3.w;
    }
    for (; e < end; e++) {
        int s0 = __ldg(&perm[e]);
        float4 v0 = __ldg(x4 + (size_t)s0 * 32 + lane);
        acc.x += v0.x; acc.y += v0.y; acc.z += v0.z; acc.w += v0.w;
    }
    float sc = (cnt > 0) ? (1.0f / (float)cnt) : 0.0f;
    acc.x *= sc; acc.y *= sc; acc.z *= sc; acc.w *= sc;
    ((float4*)aggr)[(size_t)warp * 32 + lane] = acc;
}

// ---------------------------------------------------------------------------
// Fused SAGE layer: out = relu( aggr @ Wl + xin @ Wr + b )   (aggr pre-scaled)
// [M,256] x [256,128] SGEMM: K<128 -> (aggr,Wl), K>=128 -> (xin,Wr).
// BM=128, BN=128, BK=16, 256 threads, 8x8 microtile.
__global__ __launch_bounds__(256) void sage_gemm(
    const float* __restrict__ aggr, const float* __restrict__ xin,
    const float* __restrict__ Wl, const float* __restrict__ Wr,
    const float* __restrict__ bias, float* __restrict__ out)
{
    __shared__ float As[16][128];   // [k][m]
    __shared__ float Bs[16][128];   // [k][n]

    const int t  = threadIdx.x;
    const int m0 = blockIdx.x * 128;
    const int ty = t >> 4;          // 0..15
    const int tx = t & 15;          // 0..15

    float acc[8][8];
#pragma unroll
    for (int i = 0; i < 8; i++)
#pragma unroll
        for (int j = 0; j < 8; j++) acc[i][j] = 0.f;

    for (int kb = 0; kb < 16; kb++) {
        const bool aph = (kb < 8);
        const float* Asrc = aph ? aggr : xin;
        const float* Bsrc = aph ? Wl : Wr;
        const int klocal = (kb & 7) * 16;

#pragma unroll
        for (int i = 0; i < 2; i++) {
            int idx = t + i * 256;
            int row = idx >> 2;
            int kc  = idx & 3;
            int gr  = m0 + row;
            float4 v = make_float4(0.f, 0.f, 0.f, 0.f);
            if (gr < N_NODES)
                v = *((const float4*)(Asrc + (size_t)gr * 128 + klocal + kc * 4));
            As[kc * 4 + 0][row] = v.x;
            As[kc * 4 + 1][row] = v.y;
            As[kc * 4 + 2][row] = v.z;
            As[kc * 4 + 3][row] = v.w;
        }
#pragma unroll
        for (int i = 0; i < 2; i++) {
            int idx = t + i * 256;
            int br  = idx >> 5;
            int bc  = idx & 31;
            float4 v = *((const float4*)(Bsrc + (size_t)(klocal + br) * 128 + bc * 4));
            *((float4*)&Bs[br][bc * 4]) = v;
        }
        __syncthreads();

#pragma unroll
        for (int k = 0; k < 16; k++) {
            float ra[8], rb[8];
#pragma unroll
            for (int i = 0; i < 8; i++) ra[i] = As[k][ty * 8 + i];
#pragma unroll
            for (int j = 0; j < 8; j++) rb[j] = Bs[k][tx * 8 + j];
#pragma unroll
            for (int i = 0; i < 8; i++)
#pragma unroll
                for (int j = 0; j < 8; j++) acc[i][j] += ra[i] * rb[j];
        }
        __syncthreads();
    }

#pragma unroll
    for (int i = 0; i < 8; i++) {
        int gr = m0 + ty * 8 + i;
        if (gr >= N_NODES) continue;
        float* orow = out + (size_t)gr * 128;
#pragma unroll
        for (int j = 0; j < 8; j += 4) {
            int col = tx * 8 + j;
            float4 v;
            v.x = fmaxf(acc[i][j + 0] + bias[col + 0], 0.f);
            v.y = fmaxf(acc[i][j + 1] + bias[col + 1], 0.f);
            v.z = fmaxf(acc[i][j + 2] + bias[col + 2], 0.f);
            v.w = fmaxf(acc[i][j + 3] + bias[col + 3], 0.f);
            *((float4*)(orow + col)) = v;
        }
    }
}

// ---------------------------------------------------------------------------
__global__ void pool_kernel(const float* __restrict__ h, float* __restrict__ pool) {
    __shared__ float4 s[256];
    int t = threadIdx.x;
    int c = t & 31;
    int rlane = t >> 5;
    float4 acc = make_float4(0.f, 0.f, 0.f, 0.f);
    const float4* h4 = (const float4*)h;
    for (int r = blockIdx.x * 8 + rlane; r < N_NODES; r += gridDim.x * 8) {
        float4 v = h4[(size_t)r * 32 + c];
        acc.x += v.x; acc.y += v.y; acc.z += v.z; acc.w += v.w;
    }
    s[t] = acc;
    __syncthreads();
    if (rlane == 0) {
#pragma unroll
        for (int i = 1; i < 8; i++) {
            float4 v = s[i * 32 + c];
            acc.x += v.x; acc.y += v.y; acc.z += v.z; acc.w += v.w;
        }
        atomicAdd(&pool[c * 4 + 0], acc.x);
        atomicAdd(&pool[c * 4 + 1], acc.y);
        atomicAdd(&pool[c * 4 + 2], acc.z);
        atomicAdd(&pool[c * 4 + 3], acc.w);
    }
}

__global__ void head_kernel(const float* __restrict__ pool,
                            const float* __restrict__ Wg,
                            const float* __restrict__ bg,
                            float* __restrict__ out) {
    int j = threadIdx.x;
    if (j >= D_LAT) return;
    float acc = bg[j];
    const float invn = 1.0f / (float)N_NODES;
#pragma unroll 8
    for (int k = 0; k < D; k++)
        acc += (pool[k] * invn) * Wg[k * D_LAT + j];
    out[j] = 1.0f / (1.0f + expf(-acc));
}

// ---------------------------------------------------------------------------
extern "C" void kernel_launch(void* const* d_in, const int* in_sizes, int n_in,
                              void* d_out, int out_size) {
    const float* x   = (const float*)d_in[0];
    const int*   ei  = (const int*)d_in[1];
    const float* Wl1 = (const float*)d_in[2];
    const float* Wr1 = (const float*)d_in[3];
    const float* b1  = (const float*)d_in[4];
    const float* Wl2 = (const float*)d_in[5];
    const float* Wr2 = (const float*)d_in[6];
    const float* b2  = (const float*)d_in[7];
    const float* Wl3 = (const float*)d_in[8];
    const float* Wr3 = (const float*)d_in[9];
    const float* b3  = (const float*)d_in[10];
    const float* Wg  = (const float*)d_in[11];
    const float* bg  = (const float*)d_in[12];
    float* out = (float*)d_out;

    const int* src = ei;
    const int* dst = ei + N_EDGES;

    float *aggr, *hA, *hB, *pool;
    int *deg, *offs, *cursor, *part, *perm;
    cudaGetSymbolAddress((void**)&aggr,   g_aggr);
    cudaGetSymbolAddress((void**)&hA,     g_hA);
    cudaGetSymbolAddress((void**)&hB,     g_hB);
    cudaGetSymbolAddress((void**)&pool,   g_pool);
    cudaGetSymbolAddress((void**)&deg,    g_deg);
    cudaGetSymbolAddress((void**)&offs,   g_offs);
    cudaGetSymbolAddress((void**)&cursor, g_cursor);
    cudaGetSymbolAddress((void**)&part,   g_part);
    cudaGetSymbolAddress((void**)&perm,   g_perm);

    const int gemm_blocks = (N_NODES + 127) / 128;      // 782
    const int aggr_blocks = (N_NODES + 7) / 8;          // 12500 (8 warps/block)
    const int edge_blocks = (N_EDGES + 255) / 256;

    // --- CSR-by-dst build (once, reused by all 3 layers) ---
    zero_i_kernel<<<SCAN_BLOCKS, 256>>>(deg, N_NODES);
    count_kernel<<<edge_blocks, 256>>>(dst, deg);
    scan1_kernel<<<SCAN_BLOCKS, 256>>>(deg, offs, part);
    scan2_kernel<<<1, 512>>>(part);
    scan3_kernel<<<SCAN_BLOCKS, 256>>>(offs, part, cursor);
    permute_kernel<<<edge_blocks, 256>>>(src, dst, cursor, perm);

    // --- layer 1: x -> hA ---
    gather_aggr<<<aggr_blocks, 256>>>(x, perm, offs, deg, aggr);
    sage_gemm<<<gemm_blocks, 256>>>(aggr, x, Wl1, Wr1, b1, hA);

    // --- layer 2: hA -> hB ---
    gather_aggr<<<aggr_blocks, 256>>>(hA, perm, offs, deg, aggr);
    sage_gemm<<<gemm_blocks, 256>>>(aggr, hA, Wl2, Wr2, b2, hB);

    // --- layer 3: hB -> hA ---
    gather_aggr<<<aggr_blocks, 256>>>(hB, perm, offs, deg, aggr);
    sage_gemm<<<gemm_blocks, 256>>>(aggr, hB, Wl3, Wr3, b3, hA);

    // --- pool + head ---
    zero_f_kernel<<<1, 128>>>(pool, D);
    pool_kernel<<<256, 256>>>(hA, pool);
    head_kernel<<<1, 64>>>(pool, Wg, bg, out);
}

// round 5
// speedup vs baseline: 3.7982x; 1.5075x over previous
#include <cuda_runtime.h>
#include <cuda_bf16.h>
#include <math.h>
#include <cstdint>

#define N_NODES 100000
#define D 128
#define D_LAT 64
#define N_EDGES 1600000
#define SCAN_BLOCKS ((N_NODES + 255) / 256)   // 391

// Scratch (device globals: allocation-free, graph-capture safe)
__device__ float g_aggr[(size_t)N_NODES * D];
__device__ float g_hA[(size_t)N_NODES * D];
__device__ float g_hB[(size_t)N_NODES * D];
__device__ float g_pool[D];
__device__ int   g_deg[N_NODES];
__device__ int   g_offs[N_NODES];
__device__ int   g_cursor[N_NODES];
__device__ int   g_part[SCAN_BLOCKS];
__device__ int   g_perm[N_EDGES];
// transposed weights, bf16 hi/lo split: [mat 0..5][n*128+k]
__device__ __nv_bfloat16 g_wh[6 * 128 * 128];
__device__ __nv_bfloat16 g_wl[6 * 128 * 128];

// ===========================================================================
// small utility kernels
// ===========================================================================
__global__ void zero_i_kernel(int* __restrict__ p, int n) {
    int i = blockIdx.x * blockDim.x + threadIdx.x;
    if (i < n) p[i] = 0;
}
__global__ void zero_f_kernel(float* __restrict__ p, int n) {
    int i = blockIdx.x * blockDim.x + threadIdx.x;
    if (i < n) p[i] = 0.f;
}
__global__ void count_kernel(const int* __restrict__ dst, int* __restrict__ deg) {
    int e = blockIdx.x * blockDim.x + threadIdx.x;
    if (e < N_EDGES) atomicAdd(&deg[dst[e]], 1);
}
__global__ void scan1_kernel(const int* __restrict__ deg,
                             int* __restrict__ offs, int* __restrict__ part) {
    __shared__ int s[256];
    int t = threadIdx.x;
    int i = blockIdx.x * 256 + t;
    int v = (i < N_NODES) ? deg[i] : 0;
    s[t] = v;
    __syncthreads();
#pragma unroll
    for (int d = 1; d < 256; d <<= 1) {
        int u = (t >= d) ? s[t - d] : 0;
        __syncthreads();
        s[t] += u;
        __syncthreads();
    }
    if (i < N_NODES) offs[i] = s[t] - v;
    if (t == 255) part[blockIdx.x] = s[255];
}
__global__ void scan2_kernel(int* __restrict__ part) {
    __shared__ int s[512];
    int t = threadIdx.x;
    int v = (t < SCAN_BLOCKS) ? part[t] : 0;
    s[t] = v;
    __syncthreads();
#pragma unroll
    for (int d = 1; d < 512; d <<= 1) {
        int u = (t >= d) ? s[t - d] : 0;
        __syncthreads();
        s[t] += u;
        __syncthreads();
    }
    if (t < SCAN_BLOCKS) part[t] = s[t] - v;
}
__global__ void scan3_kernel(int* __restrict__ offs, const int* __restrict__ part,
                             int* __restrict__ cursor) {
    int i = blockIdx.x * blockDim.x + threadIdx.x;
    if (i < N_NODES) {
        int o = offs[i] + part[i >> 8];
        offs[i] = o;
        cursor[i] = o;
    }
}
__global__ void permute_kernel(const int* __restrict__ src, const int* __restrict__ dst,
                               int* __restrict__ cursor, int* __restrict__ perm) {
    int e = blockIdx.x * blockDim.x + threadIdx.x;
    if (e < N_EDGES) {
        int pos = atomicAdd(&cursor[dst[e]], 1);
        perm[pos] = src[e];
    }
}

// transpose W [k][n] -> WT [n][k], split into bf16 hi + bf16 residual lo
__global__ void prep_w_kernel(const float* __restrict__ W,
                              __nv_bfloat16* __restrict__ Th,
                              __nv_bfloat16* __restrict__ Tl) {
    int t = blockIdx.x * 256 + threadIdx.x;
    if (t >= 128 * 128) return;
    int n = t >> 7, k = t & 127;
    float w = W[k * 128 + n];
    __nv_bfloat16 h = __float2bfloat16(w);
    float lo = w - __bfloat162float(h);
    Th[t] = h;
    Tl[t] = __float2bfloat16(lo);
}

// ===========================================================================
// gather-based mean aggregation: one warp per node
// ===========================================================================
__global__ __launch_bounds__(256) void gather_aggr(
    const float* __restrict__ x, const int* __restrict__ perm,
    const int* __restrict__ offs, const int* __restrict__ deg,
    float* __restrict__ aggr)
{
    int warp = (blockIdx.x * blockDim.x + threadIdx.x) >> 5;
    int lane = threadIdx.x & 31;
    if (warp >= N_NODES) return;
    int beg = __ldg(&offs[warp]);
    int cnt = __ldg(&deg[warp]);
    int end = beg + cnt;
    const float4* x4 = (const float4*)x;

    float4 acc = make_float4(0.f, 0.f, 0.f, 0.f);
    int e = beg;
    for (; e + 4 <= end; e += 4) {
        int s0 = __ldg(&perm[e + 0]);
        int s1 = __ldg(&perm[e + 1]);
        int s2 = __ldg(&perm[e + 2]);
        int s3 = __ldg(&perm[e + 3]);
        float4 v0 = __ldg(x4 + (size_t)s0 * 32 + lane);
        float4 v1 = __ldg(x4 + (size_t)s1 * 32 + lane);
        float4 v2 = __ldg(x4 + (size_t)s2 * 32 + lane);
        float4 v3 = __ldg(x4 + (size_t)s3 * 32 + lane);
        acc.x += v0.x + v1.x + v2.x + v3.x;
        acc.y += v0.y + v1.y + v2.y + v3.y;
        acc.z += v0.z + v1.z + v2.z + v3.z;
        acc.w += v0.w + v1.w + v2.w + v3.w;
    }
    for (; e < end; e++) {
        int s0 = __ldg(&perm[e]);
        float4 v0 = __ldg(x4 + (size_t)s0 * 32 + lane);
        acc.x += v0.x; acc.y += v0.y; acc.z += v0.z; acc.w += v0.w;
    }
    float sc = (cnt > 0) ? (1.0f / (float)cnt) : 0.0f;
    acc.x *= sc; acc.y *= sc; acc.z *= sc; acc.w *= sc;
    ((float4*)aggr)[(size_t)warp * 32 + lane] = acc;
}

// ===========================================================================
// bf16x3 mma.sync fused SAGE layer:
//   out = relu( aggr @ Wl + xin @ Wr + b )
// A and W split hi/lo bf16; computes Ah*Wh + Ah*Wl + Al*Wh (fp32 accum).
// CTA tile 128x128, warp tile 64x32 (2x4 warp grid), K = 256 in 8 chunks of 32.
// ===========================================================================
#define A_STRIDE 80   // bytes per 32-bf16 row (64B data + 16B pad): 16B-aligned,
                      // bank = (g*20 + tig) mod 32 -> all 32 lanes distinct
#define TILE_BYTES (128 * A_STRIDE)  // 10240

__device__ __forceinline__ void mma_bf16(float* c, const uint32_t* a,
                                         uint32_t b0, uint32_t b1) {
    asm volatile(
        "mma.sync.aligned.m16n8k16.row.col.f32.bf16.bf16.f32 "
        "{%0,%1,%2,%3}, {%4,%5,%6,%7}, {%8,%9}, {%0,%1,%2,%3};\n"
        : "+f"(c[0]), "+f"(c[1]), "+f"(c[2]), "+f"(c[3])
        : "r"(a[0]), "r"(a[1]), "r"(a[2]), "r"(a[3]), "r"(b0), "r"(b1));
}

__global__ __launch_bounds__(256, 2) void sage_gemm_mma(
    const float* __restrict__ aggr, const float* __restrict__ xin,
    const __nv_bfloat16* __restrict__ WlTh, const __nv_bfloat16* __restrict__ WlTl,
    const __nv_bfloat16* __restrict__ WrTh, const __nv_bfloat16* __restrict__ WrTl,
    const float* __restrict__ bias, float* __restrict__ out)
{
    __shared__ char sAh[TILE_BYTES];
    __shared__ char sAl[TILE_BYTES];
    __shared__ char sWh[TILE_BYTES];
    __shared__ char sWl[TILE_BYTES];

    const int t    = threadIdx.x;
    const int wid  = t >> 5;
    const int lane = t & 31;
    const int g    = lane >> 2;      // group 0..7
    const int tig  = lane & 3;       // thread-in-group
    const int warpM = wid >> 2;      // 0..1 -> 64 rows each
    const int warpN = wid & 3;       // 0..3 -> 32 cols each
    const int m0 = blockIdx.x * 128;

    float acc[4][4][4];
#pragma unroll
    for (int i = 0; i < 4; i++)
#pragma unroll
        for (int j = 0; j < 4; j++)
#pragma unroll
            for (int r = 0; r < 4; r++) acc[i][j][r] = 0.f;

    // A-load role: row = t>>1 (0..127), half = t&1 -> k cols [half*16, half*16+16)
    const int arow  = t >> 1;
    const int ahalf = t & 1;

    for (int c = 0; c < 8; c++) {
        const bool fh = (c < 4);
        const float* Asrc = fh ? aggr : xin;
        const __nv_bfloat16* Whs = fh ? WlTh : WrTh;
        const __nv_bfloat16* Wls = fh ? WlTl : WrTl;
        const int k0 = (c & 3) * 32;

        // ---- load & split A chunk: rows 128 x 32 k (fp32 -> bf16 hi/lo)
        {
            int gr = m0 + arow;
            const float4* srcp = (const float4*)(Asrc + (size_t)gr * 128 + k0 + ahalf * 16);
#pragma unroll
            for (int j = 0; j < 4; j++) {
                float4 v = make_float4(0.f, 0.f, 0.f, 0.f);
                if (gr < N_NODES) v = __ldg(srcp + j);
                __nv_bfloat16 h0 = __float2bfloat16(v.x);
                __nv_bfloat16 h1 = __float2bfloat16(v.y);
                __nv_bfloat16 h2 = __float2bfloat16(v.z);
                __nv_bfloat16 h3 = __float2bfloat16(v.w);
                __nv_bfloat16 l0 = __float2bfloat16(v.x - __bfloat162float(h0));
                __nv_bfloat16 l1 = __float2bfloat16(v.y - __bfloat162float(h1));
                __nv_bfloat16 l2 = __float2bfloat16(v.z - __bfloat162float(h2));
                __nv_bfloat16 l3 = __float2bfloat16(v.w - __bfloat162float(h3));
                uint32_t hp0 = (uint32_t)__bfloat16_as_ushort(h0) |
                               ((uint32_t)__bfloat16_as_ushort(h1) << 16);
                uint32_t hp1 = (uint32_t)__bfloat16_as_ushort(h2) |
                               ((uint32_t)__bfloat16_as_ushort(h3) << 16);
                uint32_t lp0 = (uint32_t)__bfloat16_as_ushort(l0) |
                               ((uint32_t)__bfloat16_as_ushort(l1) << 16);
                uint32_t lp1 = (uint32_t)__bfloat16_as_ushort(l2) |
                               ((uint32_t)__bfloat16_as_ushort(l3) << 16);
                int off = arow * A_STRIDE + (ahalf * 16 + j * 4) * 2;
                *((uint2*)(sAh + off)) = make_uint2(hp0, hp1);
                *((uint2*)(sAl + off)) = make_uint2(lp0, lp1);
            }
        }
        // ---- load W chunk: 128 n-rows x 32 k bf16, hi (t<128) / lo (t>=128)
        {
            int n = t & 127;
            const __nv_bfloat16* wsrc = (t < 128) ? Whs : Wls;
            char* wdst = (t < 128) ? sWh : sWl;
            const uint4* src16 = (const uint4*)(wsrc + n * 128 + k0);
            uint4 v0 = __ldg(src16 + 0);
            uint4 v1 = __ldg(src16 + 1);
            uint4 v2 = __ldg(src16 + 2);
            uint4 v3 = __ldg(src16 + 3);
            char* row = wdst + n * A_STRIDE;
            *((uint4*)(row + 0))  = v0;
            *((uint4*)(row + 16)) = v1;
            *((uint4*)(row + 32)) = v2;
            *((uint4*)(row + 48)) = v3;
        }
        __syncthreads();

        // ---- compute: 2 k16-steps
#pragma unroll
        for (int kk = 0; kk < 2; kk++) {
            const int kb = kk * 32;   // byte offset of k16 step
            uint32_t ah[4][4], al[4][4];
#pragma unroll
            for (int mi = 0; mi < 4; mi++) {
                int rb = warpM * 64 + mi * 16;
                int r1 = (rb + g) * A_STRIDE + kb + tig * 4;
                int r2 = (rb + g + 8) * A_STRIDE + kb + tig * 4;
                ah[mi][0] = *((uint32_t*)(sAh + r1));
                ah[mi][1] = *((uint32_t*)(sAh + r2));
                ah[mi][2] = *((uint32_t*)(sAh + r1 + 16));
                ah[mi][3] = *((uint32_t*)(sAh + r2 + 16));
                al[mi][0] = *((uint32_t*)(sAl + r1));
                al[mi][1] = *((uint32_t*)(sAl + r2));
                al[mi][2] = *((uint32_t*)(sAl + r1 + 16));
                al[mi][3] = *((uint32_t*)(sAl + r2 + 16));
            }
#pragma unroll
            for (int ni = 0; ni < 4; ni++) {
                int nrow = warpN * 32 + ni * 8 + g;
                int wo = nrow * A_STRIDE + kb + tig * 4;
                uint32_t wh0 = *((uint32_t*)(sWh + wo));
                uint32_t wh1 = *((uint32_t*)(sWh + wo + 16));
                uint32_t wl0 = *((uint32_t*)(sWl + wo));
                uint32_t wl1 = *((uint32_t*)(sWl + wo + 16));
#pragma unroll
                for (int mi = 0; mi < 4; mi++) {
                    mma_bf16(acc[mi][ni], ah[mi], wh0, wh1);
                    mma_bf16(acc[mi][ni], ah[mi], wl0, wl1);
                    mma_bf16(acc[mi][ni], al[mi], wh0, wh1);
                }
            }
        }
        __syncthreads();
    }

    // ---- epilogue: bias + relu, direct global stores
#pragma unroll
    for (int mi = 0; mi < 4; mi++) {
        int r1 = m0 + warpM * 64 + mi * 16 + g;
        int r2 = r1 + 8;
#pragma unroll
        for (int ni = 0; ni < 4; ni++) {
            int col = warpN * 32 + ni * 8 + tig * 2;
            float b0 = __ldg(&bias[col]);
            float b1 = __ldg(&bias[col + 1]);
            if (r1 < N_NODES) {
                float2 v;
                v.x = fmaxf(acc[mi][ni][0] + b0, 0.f);
                v.y = fmaxf(acc[mi][ni][1] + b1, 0.f);
                *((float2*)(out + (size_t)r1 * 128 + col)) = v;
            }
            if (r2 < N_NODES) {
                float2 v;
                v.x = fmaxf(acc[mi][ni][2] + b0, 0.f);
                v.y = fmaxf(acc[mi][ni][3] + b1, 0.f);
                *((float2*)(out + (size_t)r2 * 128 + col)) = v;
            }
        }
    }
}

// ===========================================================================
__global__ void pool_kernel(const float* __restrict__ h, float* __restrict__ pool) {
    __shared__ float4 s[256];
    int t = threadIdx.x;
    int c = t & 31;
    int rlane = t >> 5;
    float4 acc = make_float4(0.f, 0.f, 0.f, 0.f);
    const float4* h4 = (const float4*)h;
    for (int r = blockIdx.x * 8 + rlane; r < N_NODES; r += gridDim.x * 8) {
        float4 v = h4[(size_t)r * 32 + c];
        acc.x += v.x; acc.y += v.y; acc.z += v.z; acc.w += v.w;
    }
    s[t] = acc;
    __syncthreads();
    if (rlane == 0) {
#pragma unroll
        for (int i = 1; i < 8; i++) {
            float4 v = s[i * 32 + c];
            acc.x += v.x; acc.y += v.y; acc.z += v.z; acc.w += v.w;
        }
        atomicAdd(&pool[c * 4 + 0], acc.x);
        atomicAdd(&pool[c * 4 + 1], acc.y);
        atomicAdd(&pool[c * 4 + 2], acc.z);
        atomicAdd(&pool[c * 4 + 3], acc.w);
    }
}

__global__ void head_kernel(const float* __restrict__ pool,
                            const float* __restrict__ Wg,
                            const float* __restrict__ bg,
                            float* __restrict__ out) {
    int j = threadIdx.x;
    if (j >= D_LAT) return;
    float acc = bg[j];
    const float invn = 1.0f / (float)N_NODES;
#pragma unroll 8
    for (int k = 0; k < D; k++)
        acc += (pool[k] * invn) * Wg[k * D_LAT + j];
    out[j] = 1.0f / (1.0f + expf(-acc));
}

// ===========================================================================
extern "C" void kernel_launch(void* const* d_in, const int* in_sizes, int n_in,
                              void* d_out, int out_size) {
    const float* x   = (const float*)d_in[0];
    const int*   ei  = (const int*)d_in[1];
    const float* W[6] = { (const float*)d_in[2], (const float*)d_in[3],   // Wl1 Wr1
                          (const float*)d_in[5], (const float*)d_in[6],   // Wl2 Wr2
                          (const float*)d_in[8], (const float*)d_in[9] }; // Wl3 Wr3
    const float* b1  = (const float*)d_in[4];
    const float* b2  = (const float*)d_in[7];
    const float* b3  = (const float*)d_in[10];
    const float* Wg  = (const float*)d_in[11];
    const float* bg  = (const float*)d_in[12];
    float* out = (float*)d_out;

    const int* src = ei;
    const int* dst = ei + N_EDGES;

    float *aggr, *hA, *hB, *pool;
    int *deg, *offs, *cursor, *part, *perm;
    __nv_bfloat16 *wh, *wl;
    cudaGetSymbolAddress((void**)&aggr,   g_aggr);
    cudaGetSymbolAddress((void**)&hA,     g_hA);
    cudaGetSymbolAddress((void**)&hB,     g_hB);
    cudaGetSymbolAddress((void**)&pool,   g_pool);
    cudaGetSymbolAddress((void**)&deg,    g_deg);
    cudaGetSymbolAddress((void**)&offs,   g_offs);
    cudaGetSymbolAddress((void**)&cursor, g_cursor);
    cudaGetSymbolAddress((void**)&part,   g_part);
    cudaGetSymbolAddress((void**)&perm,   g_perm);
    cudaGetSymbolAddress((void**)&wh,     g_wh);
    cudaGetSymbolAddress((void**)&wl,     g_wl);

    const int gemm_blocks = (N_NODES + 127) / 128;      // 782
    const int aggr_blocks = (N_NODES + 7) / 8;          // 12500
    const int edge_blocks = (N_EDGES + 255) / 256;

    // --- weight prep: transpose + bf16 hi/lo split ---
    for (int m = 0; m < 6; m++)
        prep_w_kernel<<<64, 256>>>(W[m], wh + (size_t)m * 16384, wl + (size_t)m * 16384);
#define WTH(m) (wh + (size_t)(m) * 16384)
#define WTL(m) (wl + (size_t)(m) * 16384)

    // --- CSR-by-dst build (once, reused by all 3 layers) ---
    zero_i_kernel<<<SCAN_BLOCKS, 256>>>(deg, N_NODES);
    count_kernel<<<edge_blocks, 256>>>(dst, deg);
    scan1_kernel<<<SCAN_BLOCKS, 256>>>(deg, offs, part);
    scan2_kernel<<<1, 512>>>(part);
    scan3_kernel<<<SCAN_BLOCKS, 256>>>(offs, part, cursor);
    permute_kernel<<<edge_blocks, 256>>>(src, dst, cursor, perm);

    // --- layer 1: x -> hA ---
    gather_aggr<<<aggr_blocks, 256>>>(x, perm, offs, deg, aggr);
    sage_gemm_mma<<<gemm_blocks, 256>>>(aggr, x, WTH(0), WTL(0), WTH(1), WTL(1), b1, hA);

    // --- layer 2: hA -> hB ---
    gather_aggr<<<aggr_blocks, 256>>>(hA, perm, offs, deg, aggr);
    sage_gemm_mma<<<gemm_blocks, 256>>>(aggr, hA, WTH(2), WTL(2), WTH(3), WTL(3), b2, hB);

    // --- layer 3: hB -> hA ---
    gather_aggr<<<aggr_blocks, 256>>>(hB, perm, offs, deg, aggr);
    sage_gemm_mma<<<gemm_blocks, 256>>>(aggr, hB, WTH(4), WTL(4), WTH(5), WTL(5), b3, hA);

    // --- pool + head ---
    zero_f_kernel<<<1, 128>>>(pool, D);
    pool_kernel<<<256, 256>>>(hA, pool);
    head_kernel<<<1, 64>>>(pool, Wg, bg, out);
}